// round 4
// baseline (speedup 1.0000x reference)
#include <cuda_runtime.h>
#include <cuda_bf16.h>
#include <math.h>
#include <stdint.h>

#define BDIM   2
#define LDIM   2048
#define DMODEL 1024
#define DINNER 2048
#define DSTATE 16
#define DTRANK 64
#define DCONV  4
#define NROWS  (BDIM * LDIM)          // 4096
#define XDBLW  (DTRANK + 2 * DSTATE)  // 96

// ---------------- f32 scratch ----------------
__device__ __align__(16) float g_xz  [(size_t)NROWS * 2 * DINNER];
__device__ __align__(16) float g_xs  [(size_t)NROWS * DINNER];
__device__ __align__(16) float g_xdbl[(size_t)NROWS * XDBLW];
__device__ __align__(16) float g_dt  [(size_t)NROWS * DINNER];

// ---------------- packed bf16 hi/lo (plain row-major [rows][K]) ----------------
__device__ __align__(16) __nv_bfloat16 g_xh [(size_t)NROWS * DMODEL];
__device__ __align__(16) __nv_bfloat16 g_xl [(size_t)NROWS * DMODEL];
__device__ __align__(16) __nv_bfloat16 g_wih[(size_t)(2*DINNER) * DMODEL];
__device__ __align__(16) __nv_bfloat16 g_wil[(size_t)(2*DINNER) * DMODEL];
__device__ __align__(16) __nv_bfloat16 g_xsh[(size_t)NROWS * DINNER];
__device__ __align__(16) __nv_bfloat16 g_xsl[(size_t)NROWS * DINNER];
__device__ __align__(16) __nv_bfloat16 g_wxh[(size_t)XDBLW * DINNER];
__device__ __align__(16) __nv_bfloat16 g_wxl[(size_t)XDBLW * DINNER];
__device__ __align__(16) __nv_bfloat16 g_dah[(size_t)NROWS * DTRANK];
__device__ __align__(16) __nv_bfloat16 g_dal[(size_t)NROWS * DTRANK];
__device__ __align__(16) __nv_bfloat16 g_wdh[(size_t)DINNER * DTRANK];
__device__ __align__(16) __nv_bfloat16 g_wdl[(size_t)DINNER * DTRANK];
__device__ __align__(16) __nv_bfloat16 g_yh [(size_t)NROWS * DINNER];
__device__ __align__(16) __nv_bfloat16 g_yl [(size_t)NROWS * DINNER];
__device__ __align__(16) __nv_bfloat16 g_woh[(size_t)DMODEL * DINNER];
__device__ __align__(16) __nv_bfloat16 g_wol[(size_t)DMODEL * DINNER];

// ---------------- helpers ----------------
__device__ __forceinline__ float softplus_f(float v) {
    return v > 20.f ? v : log1pf(expf(v));
}
__device__ __forceinline__ uint32_t smem_u32(const void* p) {
    uint32_t a;
    asm("{ .reg .u64 t; cvta.to.shared.u64 t, %1; cvt.u32.u64 %0, t; }" : "=r"(a) : "l"(p));
    return a;
}

#define CP_ASYNC16(dst, src, srcsize) \
    asm volatile("cp.async.cg.shared.global [%0], [%1], 16, %2;" \
        :: "r"(dst), "l"(src), "r"(srcsize) : "memory")
#define CP_COMMIT()  asm volatile("cp.async.commit_group;" ::: "memory")
#define CP_WAIT0()   asm volatile("cp.async.wait_group 0;" ::: "memory")
#define CP_WAIT1()   asm volatile("cp.async.wait_group 1;" ::: "memory")

#define LDSM_X4(r0, r1, r2, r3, addr) \
    asm volatile("ldmatrix.sync.aligned.m8n8.x4.shared.b16 {%0,%1,%2,%3}, [%4];" \
        : "=r"(r0), "=r"(r1), "=r"(r2), "=r"(r3) : "r"(addr))

__device__ __forceinline__ void mma16816(float* c, const uint32_t* a, uint32_t b0, uint32_t b1) {
    asm volatile(
        "mma.sync.aligned.m16n8k16.row.col.f32.bf16.bf16.f32 "
        "{%0,%1,%2,%3}, {%4,%5,%6,%7}, {%8,%9}, {%0,%1,%2,%3};\n"
        : "+f"(c[0]), "+f"(c[1]), "+f"(c[2]), "+f"(c[3])
        : "r"(a[0]), "r"(a[1]), "r"(a[2]), "r"(a[3]), "r"(b0), "r"(b1));
}

// SW128-style XOR swizzle for 128B rows, 16B granularity
__device__ __forceinline__ uint32_t sw_off(int row, int cb) {
    return (uint32_t)((row * 128 + cb) ^ ((row & 7) << 4));
}

// ============ pack fp32 -> plain row-major bf16 hi/lo ============
__global__ __launch_bounds__(256) void pack_plain(
    const float* __restrict__ src, int ldsrc, int K,
    __nv_bfloat16* __restrict__ hi, __nv_bfloat16* __restrict__ lo, int total8)
{
    const int idx = blockIdx.x * 256 + threadIdx.x;
    if (idx >= total8) return;
    const int kd = K >> 3;
    const int m  = idx / kd;
    const int k  = (idx - m * kd) << 3;
    const float4 a = *(const float4*)&src[(size_t)m * ldsrc + k];
    const float4 b = *(const float4*)&src[(size_t)m * ldsrc + k + 4];
    const float v[8] = {a.x, a.y, a.z, a.w, b.x, b.y, b.z, b.w};
    __nv_bfloat16 h[8], l[8];
#pragma unroll
    for (int e = 0; e < 8; e++) {
        h[e] = __float2bfloat16(v[e]);
        l[e] = __float2bfloat16(v[e] - __bfloat162float(h[e]));
    }
    *(uint4*)(hi + (size_t)m * K + k) = *(const uint4*)h;
    *(uint4*)(lo + (size_t)m * K + k) = *(const uint4*)l;
}

// ============ GEMM: C = A(M,K) * W(N,K)^T, bf16 split-2 (3 MMAs), cp.async+ldmatrix ============
// 128x128 CTA tile, BK=64, double-buffered, 256 threads (8 warps: 2m x 4n, warp=64x32)
// EPI: 0 none, 1 softplus(acc + bias[col])
template<int EPI>
__global__ __launch_bounds__(256) void gemm_mma2(
    const __nv_bfloat16* __restrict__ Ah, const __nv_bfloat16* __restrict__ Al,
    const __nv_bfloat16* __restrict__ Wh, const __nv_bfloat16* __restrict__ Wl,
    float* __restrict__ C, int ldc, int N, int K, const float* __restrict__ bias)
{
    constexpr int TILE  = 128 * 128;       // bytes per operand tile (128 rows x 64 bf16)
    constexpr int STAGE = 4 * TILE;        // 64 KB

    extern __shared__ char sm[];
    const uint32_t smBase = smem_u32(sm);

    const int tid  = threadIdx.x;
    const int lane = tid & 31;
    const int warp = tid >> 5;
    const int wr = warp >> 2;              // 0..1  (m)
    const int wc = warp & 3;               // 0..3  (n)
    const int mBase = blockIdx.y * 128;
    const int nBase = blockIdx.x * 128;

    const int ldRow = tid >> 3;            // 0..31
    const int ldC   = tid & 7;             // 16B chunk 0..7

    const int nk = K >> 6;

    // ---- loader ----
    auto issue = [&](int c, int s) {
        const int k0 = c << 6;
        const uint32_t st = smBase + s * STAGE;
#pragma unroll
        for (int t = 0; t < 4; t++) {
            const int row = ldRow + t * 32;
            const uint32_t so = sw_off(row, ldC * 16);
            const size_t aoff = (size_t)(mBase + row) * K + k0 + ldC * 8;
            CP_ASYNC16(st + so,            Ah + aoff, 16);
            CP_ASYNC16(st + TILE + so,     Al + aoff, 16);
            const int wrow = nBase + row;
            const int ok = (wrow < N) ? 16 : 0;
            const size_t woff = (size_t)(ok ? wrow : 0) * K + k0 + ldC * 8;
            CP_ASYNC16(st + 2 * TILE + so, Wh + woff, ok);
            CP_ASYNC16(st + 3 * TILE + so, Wl + woff, ok);
        }
        CP_COMMIT();
    };

    float acc[4][4][4];
#pragma unroll
    for (int i = 0; i < 4; i++)
#pragma unroll
        for (int j = 0; j < 4; j++)
#pragma unroll
            for (int e = 0; e < 4; e++) acc[i][j][e] = 0.f;

    issue(0, 0);
    if (nk > 1) issue(1, 1);

    const int lr = lane & 15;
    const int lc = lane >> 4;

    for (int c = 0; c < nk; c++) {
        if (c == nk - 1) { CP_WAIT0(); } else { CP_WAIT1(); }
        __syncthreads();

        const uint32_t st  = smBase + (c & 1) * STAGE;
        const uint32_t aHi = st;
        const uint32_t aLo = st + TILE;
        const uint32_t wHi = st + 2 * TILE;
        const uint32_t wLo = st + 3 * TILE;

#pragma unroll
        for (int k16 = 0; k16 < 4; k16++) {
            const int cb = k16 * 32 + lc * 16;
            uint32_t bh[8], bl[8];
            {
                const int r0 = wc * 32 + lr;
                const int r1 = wc * 32 + 16 + lr;
                const uint32_t o0 = sw_off(r0, cb);
                const uint32_t o1 = sw_off(r1, cb);
                LDSM_X4(bh[0], bh[1], bh[2], bh[3], wHi + o0);
                LDSM_X4(bh[4], bh[5], bh[6], bh[7], wHi + o1);
                LDSM_X4(bl[0], bl[1], bl[2], bl[3], wLo + o0);
                LDSM_X4(bl[4], bl[5], bl[6], bl[7], wLo + o1);
            }
#pragma unroll
            for (int i = 0; i < 4; i++) {
                const int rowA = wr * 64 + i * 16 + lr;
                const uint32_t oA = sw_off(rowA, cb);
                uint32_t ah[4], al[4];
                LDSM_X4(ah[0], ah[1], ah[2], ah[3], aHi + oA);
                LDSM_X4(al[0], al[1], al[2], al[3], aLo + oA);
#pragma unroll
                for (int j = 0; j < 4; j++) {
                    const int jj = j >> 1, sel = j & 1;
                    const uint32_t b0h = bh[jj * 4 + sel], b1h = bh[jj * 4 + sel + 2];
                    const uint32_t b0l = bl[jj * 4 + sel], b1l = bl[jj * 4 + sel + 2];
                    mma16816(acc[i][j], ah, b0h, b1h);   // hi*hi
                    mma16816(acc[i][j], al, b0h, b1h);   // lo*hi
                    mma16816(acc[i][j], ah, b0l, b1l);   // hi*lo
                }
            }
        }

        if (c + 2 < nk) {
            __syncthreads();
            issue(c + 2, c & 1);
        }
    }

    // ---- epilogue: direct register stores ----
#pragma unroll
    for (int i = 0; i < 4; i++) {
        const int m0 = mBase + wr * 64 + i * 16 + (lane >> 2);
#pragma unroll
        for (int j = 0; j < 4; j++) {
            const int col = nBase + wc * 32 + j * 8 + 2 * (lane & 3);
            if (col < N) {
                float2 v0 = make_float2(acc[i][j][0], acc[i][j][1]);
                float2 v1 = make_float2(acc[i][j][2], acc[i][j][3]);
                if (EPI == 1) {
                    const float b0 = bias[col], b1 = bias[col + 1];
                    v0.x = softplus_f(v0.x + b0);
                    v0.y = softplus_f(v0.y + b1);
                    v1.x = softplus_f(v1.x + b0);
                    v1.y = softplus_f(v1.y + b1);
                }
                *(float2*)&C[(size_t)m0 * ldc + col] = v0;
                *(float2*)&C[(size_t)(m0 + 8) * ldc + col] = v1;
            }
        }
    }
}

// ---------------- causal depthwise conv (k=4) + bias + SiLU, fused bf16 split ----------------
#define CONV_LT 128
__global__ __launch_bounds__(256) void conv_silu_kernel(
    const float* __restrict__ cw, const float* __restrict__ cb)
{
    const int d  = blockIdx.x * 256 + threadIdx.x;
    const int b  = blockIdx.z;
    const int l0 = blockIdx.y * CONV_LT;

    const float w0 = cw[d * 4 + 0], w1 = cw[d * 4 + 1];
    const float w2 = cw[d * 4 + 2], w3 = cw[d * 4 + 3];
    const float bias = cb[d];

    const float* xp = g_xz + (size_t)b * LDIM * (2 * DINNER) + d;
    float xm3 = (l0 - 3 >= 0) ? xp[(size_t)(l0 - 3) * (2 * DINNER)] : 0.f;
    float xm2 = (l0 - 2 >= 0) ? xp[(size_t)(l0 - 2) * (2 * DINNER)] : 0.f;
    float xm1 = (l0 - 1 >= 0) ? xp[(size_t)(l0 - 1) * (2 * DINNER)] : 0.f;

    for (int l = l0; l < l0 + CONV_LT; l++) {
        const float xc = xp[(size_t)l * (2 * DINNER)];
        const float acc = bias + w0 * xm3 + w1 * xm2 + w2 * xm1 + w3 * xc;
        const float s = acc / (1.f + __expf(-acc));
        const size_t o = ((size_t)b * LDIM + l) * DINNER + d;
        g_xs[o] = s;
        const __nv_bfloat16 h = __float2bfloat16(s);
        g_xsh[o] = h;
        g_xsl[o] = __float2bfloat16(s - __bfloat162float(h));
        xm3 = xm2; xm2 = xm1; xm1 = xc;
    }
}

// ---------------- selective scan + D skip + SiLU(z) gate, fused bf16 split out ----------------
__global__ __launch_bounds__(128) void scan_kernel(
    const float* __restrict__ A_log, const float* __restrict__ Dvec)
{
    const int b    = blockIdx.y;
    const int tid  = threadIdx.x;
    const int sub  = tid & 3;
    const int dloc = tid >> 2;
    const int d    = blockIdx.x * 32 + dloc;
    const int n0   = sub * 4;

    __shared__ float Bsh[32][DSTATE];
    __shared__ float Csh[32][DSTATE];

    float a[4], h[4];
#pragma unroll
    for (int n = 0; n < 4; n++) {
        a[n] = -__expf(A_log[d * DSTATE + n0 + n]);
        h[n] = 0.f;
    }
    const float Dd = Dvec[d];
    const size_t rowBase = (size_t)b * LDIM;

    for (int t0 = 0; t0 < LDIM; t0 += 32) {
        __syncthreads();
        for (int i = tid; i < 32 * 32; i += 128) {
            const int tl = i >> 5;
            const int c  = i & 31;
            const float v = g_xdbl[(rowBase + t0 + tl) * XDBLW + DTRANK + c];
            if (c < DSTATE) Bsh[tl][c] = v;
            else            Csh[tl][c - DSTATE] = v;
        }
        __syncthreads();

#pragma unroll 4
        for (int tl = 0; tl < 32; tl++) {
            const size_t r = rowBase + t0 + tl;
            const float dt = g_dt[r * DINNER + d];
            const float x  = g_xs[r * DINNER + d];
            const float z  = g_xz[r * (2 * DINNER) + DINNER + d];
            const float dtx = dt * x;
            float y = 0.f;
#pragma unroll
            for (int n = 0; n < 4; n++) {
                const float dA = __expf(dt * a[n]);
                h[n] = h[n] * dA + dtx * Bsh[tl][n0 + n];
                y += h[n] * Csh[tl][n0 + n];
            }
            y += __shfl_xor_sync(0xffffffffu, y, 1);
            y += __shfl_xor_sync(0xffffffffu, y, 2);
            y += Dd * x;
            const float sz = z / (1.f + __expf(-z));
            if (sub == 0) {
                const float yv = y * sz;
                const __nv_bfloat16 hh = __float2bfloat16(yv);
                g_yh[r * DINNER + d] = hh;
                g_yl[r * DINNER + d] = __float2bfloat16(yv - __bfloat162float(hh));
            }
        }
    }
}

// ---------------- launch ----------------
extern "C" void kernel_launch(void* const* d_in, const int* in_sizes, int n_in,
                              void* d_out, int out_size)
{
    const float* x       = (const float*)d_in[0];
    const float* W_in    = (const float*)d_in[1];
    const float* conv_w  = (const float*)d_in[2];
    const float* conv_b  = (const float*)d_in[3];
    const float* W_xproj = (const float*)d_in[4];
    const float* W_dt    = (const float*)d_in[5];
    const float* b_dt    = (const float*)d_in[6];
    const float* A_log   = (const float*)d_in[7];
    const float* Dvec    = (const float*)d_in[8];
    const float* W_out   = (const float*)d_in[9];
    float* out = (float*)d_out;

    float *xz, *xdbl, *dtb;
    cudaGetSymbolAddress((void**)&xz,   g_xz);
    cudaGetSymbolAddress((void**)&xdbl, g_xdbl);
    cudaGetSymbolAddress((void**)&dtb,  g_dt);

    __nv_bfloat16 *xh, *xl, *wih, *wil, *xsh, *xsl, *wxh, *wxl;
    __nv_bfloat16 *dah, *dal, *wdh, *wdl, *yh, *yl, *woh, *wol;
    cudaGetSymbolAddress((void**)&xh,  g_xh);  cudaGetSymbolAddress((void**)&xl,  g_xl);
    cudaGetSymbolAddress((void**)&wih, g_wih); cudaGetSymbolAddress((void**)&wil, g_wil);
    cudaGetSymbolAddress((void**)&xsh, g_xsh); cudaGetSymbolAddress((void**)&xsl, g_xsl);
    cudaGetSymbolAddress((void**)&wxh, g_wxh); cudaGetSymbolAddress((void**)&wxl, g_wxl);
    cudaGetSymbolAddress((void**)&dah, g_dah); cudaGetSymbolAddress((void**)&dal, g_dal);
    cudaGetSymbolAddress((void**)&wdh, g_wdh); cudaGetSymbolAddress((void**)&wdl, g_wdl);
    cudaGetSymbolAddress((void**)&yh,  g_yh);  cudaGetSymbolAddress((void**)&yl,  g_yl);
    cudaGetSymbolAddress((void**)&woh, g_woh); cudaGetSymbolAddress((void**)&wol, g_wol);

    constexpr int SMEM = 2 * 4 * 128 * 128;  // 131072 B
    cudaFuncSetAttribute((const void*)gemm_mma2<0>,
                         cudaFuncAttributeMaxDynamicSharedMemorySize, SMEM);
    cudaFuncSetAttribute((const void*)gemm_mma2<1>,
                         cudaFuncAttributeMaxDynamicSharedMemorySize, SMEM);

    // ---- packs for in_proj ----
    {
        int t8 = NROWS * DMODEL / 8;
        pack_plain<<<(t8 + 255) / 256, 256>>>(x, DMODEL, DMODEL, xh, xl, t8);
        t8 = 2 * DINNER * DMODEL / 8;
        pack_plain<<<(t8 + 255) / 256, 256>>>(W_in, DMODEL, DMODEL, wih, wil, t8);
    }

    // 1. in_proj: xz = x @ W_in^T  (M=4096, N=4096, K=1024)
    gemm_mma2<0><<<dim3(4096 / 128, 32), 256, SMEM>>>(
        xh, xl, wih, wil, xz, 2 * DINNER, 2 * DINNER, DMODEL, nullptr);

    // 2. conv + SiLU (+ bf16 split of xs)
    conv_silu_kernel<<<dim3(DINNER / 256, LDIM / CONV_LT, BDIM), 256>>>(conv_w, conv_b);

    // ---- pack W_xproj ----
    {
        int t8 = XDBLW * DINNER / 8;
        pack_plain<<<(t8 + 255) / 256, 256>>>(W_xproj, DINNER, DINNER, wxh, wxl, t8);
    }

    // 3. x_proj: x_dbl = xs @ W_xproj^T  (M=4096, N=96, K=2048)
    gemm_mma2<0><<<dim3(1, 32), 256, SMEM>>>(
        xsh, xsl, wxh, wxl, xdbl, XDBLW, XDBLW, DINNER, nullptr);

    // ---- packs for dt gemm ----
    {
        int t8 = NROWS * DTRANK / 8;
        pack_plain<<<(t8 + 255) / 256, 256>>>(xdbl, XDBLW, DTRANK, dah, dal, t8);
        t8 = DINNER * DTRANK / 8;
        pack_plain<<<(t8 + 255) / 256, 256>>>(W_dt, DTRANK, DTRANK, wdh, wdl, t8);
    }

    // 4. dt = softplus(x_dbl[:, :64] @ W_dt^T + b_dt)  (M=4096, N=2048, K=64)
    gemm_mma2<1><<<dim3(DINNER / 128, 32), 256, SMEM>>>(
        dah, dal, wdh, wdl, dtb, DINNER, DINNER, DTRANK, b_dt);

    // 5. selective scan + D skip + gate (+ bf16 split of y)
    scan_kernel<<<dim3(DINNER / 32, BDIM), 128>>>(A_log, Dvec);

    // ---- pack W_out ----
    {
        int t8 = DMODEL * DINNER / 8;
        pack_plain<<<(t8 + 255) / 256, 256>>>(W_out, DINNER, DINNER, woh, wol, t8);
    }

    // 6. out_proj: out = y @ W_out^T  (M=4096, N=1024, K=2048)
    gemm_mma2<0><<<dim3(DMODEL / 128, 32), 256, SMEM>>>(
        yh, yl, woh, wol, out, DMODEL, DMODEL, DINNER, nullptr);
}